// round 5
// baseline (speedup 1.0000x reference)
#include <cuda_runtime.h>
#include <stdint.h>

// Problem constants (fixed by the reference)
#define N_POI   10000
#define V_VOCAB 20000
#define BS      6400          // B*S = 64*100
#define N_VEC   (N_POI / 4)   // 2500 float4 per row
#define BIG_INV (1.0f / 9999999.99f)

// Scratch: resolved row index per (b,s). Device global (no allocation allowed).
__device__ int g_rowidx[BS];

// ---------------------------------------------------------------------------
// Prep: resolve venueid2coor[inputs_poi] -> row index, with runtime dtype
// detection (int64 vs int32). For int64 little-endian values in [0, N_POI)
// the upper 32-bit word of every 8-byte element is zero; for int32 data the
// upper word aliases the next element (random in [0,10000)), so 32 samples
// all being zero has probability ~1e-128. Deterministic & graph-safe.
// ---------------------------------------------------------------------------
__global__ void prep_indices(const void* __restrict__ v2c_raw,
                             const void* __restrict__ poi_raw) {
    __shared__ int s_is64;
    if (threadIdx.x == 0) {
        const unsigned long long* p = (const unsigned long long*)v2c_raw;
        int is64 = 1;
        #pragma unroll
        for (int i = 0; i < 32; i++) {
            if ((p[i] >> 32) != 0ull) { is64 = 0; break; }
        }
        s_is64 = is64;
    }
    __syncthreads();
    const int is64 = s_is64;

    for (int i = blockIdx.x * blockDim.x + threadIdx.x; i < BS;
         i += gridDim.x * blockDim.x) {
        long long vid, row;
        if (is64) {
            vid = ((const long long*)poi_raw)[i];
            row = ((const long long*)v2c_raw)[vid];
        } else {
            vid = (long long)((const int*)poi_raw)[i];
            row = (long long)((const int*)v2c_raw)[vid];
        }
        g_rowidx[i] = (int)row;
    }
}

// ---------------------------------------------------------------------------
// Main: one block per output row. Coalesced float4 streaming of the gathered
// distance-matrix row; reciprocal with the zero->BIG mask fused.
// 10000 floats/row, row byte-stride 40000 (16B aligned) -> float4 is safe.
// ---------------------------------------------------------------------------
__global__ void __launch_bounds__(256)
gather_recip_kernel(const float* __restrict__ mat, float* __restrict__ out) {
    const int orow = blockIdx.x;                 // 0..BS-1
    const int srow = g_rowidx[orow];             // gathered matrix row

    const float4* __restrict__ src =
        (const float4*)(mat + (long long)srow * N_POI);
    float4* __restrict__ dst =
        (float4*)(out + (long long)orow * N_POI);

    for (int c = threadIdx.x; c < N_VEC; c += blockDim.x) {
        float4 v = src[c];
        float4 o;
        o.x = (v.x == 0.0f) ? BIG_INV : __fdividef(1.0f, v.x);
        o.y = (v.y == 0.0f) ? BIG_INV : __fdividef(1.0f, v.y);
        o.z = (v.z == 0.0f) ? BIG_INV : __fdividef(1.0f, v.z);
        o.w = (v.w == 0.0f) ? BIG_INV : __fdividef(1.0f, v.w);
        dst[c] = o;
    }
}

// ---------------------------------------------------------------------------
// Input order (setup_inputs dict order):
//   d_in[0] = venueid2coor  [V_VOCAB]   int (64- or 32-bit, detected)
//   d_in[1] = inputs_poi    [B*S]       int (same dtype)
//   d_in[2] = poi_distance_matrix [N_POI*N_POI] float32
// out: [B, S, N_POI] float32
// ---------------------------------------------------------------------------
extern "C" void kernel_launch(void* const* d_in, const int* in_sizes, int n_in,
                              void* d_out, int out_size) {
    const void*  v2c = d_in[0];
    const void*  poi = d_in[1];
    const float* mat = (const float*)d_in[2];
    float*       out = (float*)d_out;

    prep_indices<<<25, 256>>>(v2c, poi);
    gather_recip_kernel<<<BS, 256>>>(mat, out);
}

// round 6
// speedup vs baseline: 1.0533x; 1.0533x over previous
#include <cuda_runtime.h>
#include <stdint.h>

// Problem constants (fixed by the reference)
#define N_POI   10000
#define V_VOCAB 20000
#define BS      6400          // B*S = 64*100
#define N_VEC   (N_POI / 4)   // 2500 float4 per row
#define BIG_INV (1.0f / 9999999.99f)

__device__ __forceinline__ float4 recip_mask(float4 v) {
    float4 o;
    o.x = (v.x == 0.0f) ? BIG_INV : __fdividef(1.0f, v.x);
    o.y = (v.y == 0.0f) ? BIG_INV : __fdividef(1.0f, v.y);
    o.z = (v.z == 0.0f) ? BIG_INV : __fdividef(1.0f, v.z);
    o.w = (v.w == 0.0f) ? BIG_INV : __fdividef(1.0f, v.w);
    return o;
}

// ---------------------------------------------------------------------------
// Fused single kernel: one block per output row.
//   - thread 0 resolves venueid2coor[inputs_poi[row]] (dtype auto-detected:
//     for int64 LE values in [0,10000) every upper 32-bit word is 0; for
//     packed int32 data 16 consecutive zero upper-words has prob ~1e-64).
//   - 256 threads stream the 10000-float row as float4 with 4 independent
//     loads in flight per iteration (MLP=4) to saturate HBM.
//   - streaming stores (evict-first) keep the gathered-row working set in L2
//     so duplicate row reads keep hitting L2 instead of DRAM.
// ---------------------------------------------------------------------------
__global__ void __launch_bounds__(256)
fused_gather_recip(const void* __restrict__ v2c_raw,
                   const void* __restrict__ poi_raw,
                   const float* __restrict__ mat,
                   float* __restrict__ out) {
    __shared__ int s_row;
    if (threadIdx.x == 0) {
        const unsigned long long* p = (const unsigned long long*)v2c_raw;
        int is64 = 1;
        #pragma unroll
        for (int i = 0; i < 16; i++) {
            if ((p[i] >> 32) != 0ull) { is64 = 0; break; }
        }
        const int orow = blockIdx.x;
        long long vid, row;
        if (is64) {
            vid = ((const long long*)poi_raw)[orow];
            row = ((const long long*)v2c_raw)[vid];
        } else {
            vid = (long long)((const int*)poi_raw)[orow];
            row = (long long)((const int*)v2c_raw)[vid];
        }
        s_row = (int)row;
    }
    __syncthreads();

    const int srow = s_row;
    const float4* __restrict__ src =
        (const float4*)(mat + (long long)srow * N_POI);
    float4* __restrict__ dst =
        (float4*)(out + (long long)blockIdx.x * N_POI);

    // N_VEC = 2500 = 2*1024 + 452. Two fully-unrolled 4x iterations with
    // front-batched loads, then a predicated remainder loop.
    #pragma unroll
    for (int base = 0; base < 2048; base += 1024) {
        const int c = base + threadIdx.x;
        float4 v0 = src[c];
        float4 v1 = src[c + 256];
        float4 v2 = src[c + 512];
        float4 v3 = src[c + 768];
        __stcs(&dst[c],       recip_mask(v0));
        __stcs(&dst[c + 256], recip_mask(v1));
        __stcs(&dst[c + 512], recip_mask(v2));
        __stcs(&dst[c + 768], recip_mask(v3));
    }
    // remainder: c in [2048, 2500) -> up to 2 iterations per thread
    {
        const int c0 = 2048 + threadIdx.x;
        const int c1 = c0 + 256;
        float4 v0, v1;
        bool p1 = (c1 < N_VEC);
        v0 = src[c0];                       // c0 < 2304 < 2500 always valid
        if (p1) v1 = src[c1];
        __stcs(&dst[c0], recip_mask(v0));
        if (p1) __stcs(&dst[c1], recip_mask(v1));
    }
}

// ---------------------------------------------------------------------------
// Input order (setup_inputs dict order):
//   d_in[0] = venueid2coor        [V_VOCAB]       int64/int32 (detected)
//   d_in[1] = inputs_poi          [B*S]           int64/int32 (same dtype)
//   d_in[2] = poi_distance_matrix [N_POI*N_POI]   float32
// out: [B, S, N_POI] float32
// ---------------------------------------------------------------------------
extern "C" void kernel_launch(void* const* d_in, const int* in_sizes, int n_in,
                              void* d_out, int out_size) {
    const void*  v2c = d_in[0];
    const void*  poi = d_in[1];
    const float* mat = (const float*)d_in[2];
    float*       out = (float*)d_out;

    fused_gather_recip<<<BS, 256>>>(v2c, poi, mat, out);
}